// round 16
// baseline (speedup 1.0000x reference)
#include <cuda_runtime.h>
#include <cstdint>

// Problem constants
#define BB 64
#define SS 512
#define HH 768
#define EE 128
#define TT_ 4
#define NT 5
#define H4 192        // H/4 float4 lanes
#define NROW (BB * SS)        // 32768 enhance rows
#define NEMB (BB * EE)        // 8192 emb tasks
#define ENH_BLOCKS 888
#define EMB_BLOCKS 296
#define GRID (ENH_BLOCKS + EMB_BLOCKS)   // 1184 = 148 SMs x 8 blocks

// Scratch (no allocs allowed). Packed per-(b,s) coefficients:
//   .x = 5 x 6-bit type counts, .y = float conf-sum (as bits)
__device__ uint2 g_coef[NROW];

// ---------------------------------------------------------------------------
// P: per-batch coefficient build. One block per batch b (512 threads, one per
// flat (e,t)). Packed histogram in smem, 8-byte store per row.
// Triggers programmatic launch of the fused kernel once stores are issued.
// ---------------------------------------------------------------------------
__global__ void __launch_bounds__(512) rowcoef_kernel(
    const int* __restrict__ ent_tokens,     // [E,T]
    const int* __restrict__ types,          // [B,E]
    const float* __restrict__ conf) {       // [B,E]
    __shared__ unsigned s_cnt[SS];
    __shared__ float s_conf[SS];
    int b = blockIdx.x;
    int tid = threadIdx.x;                  // 0..511 == flat (e,t)

    s_cnt[tid] = 0u;
    s_conf[tid] = 0.f;
    __syncthreads();

    int tok = ent_tokens[tid];
    int e = tid >> 2;
    int ty = types[b * EE + e];
    float c = conf[b * EE + e];
    atomicAdd(&s_cnt[tok], 1u << (6 * ty));
    atomicAdd(&s_conf[tok], c);
    __syncthreads();

    g_coef[b * SS + tid] = make_uint2(s_cnt[tid], __float_as_uint(s_conf[tid]));

    cudaTriggerProgrammaticLaunchCompletion();
}

// ---------------------------------------------------------------------------
// Fused main kernel with STATIC ROLE SPLIT:
//   blocks 0..887   : enhance rows, stride 888 over dense row space —
//                     all addressing is constant pointer increments.
//   blocks 888..1183: emb tasks, stride 296 over 8192 tasks (shift/mask
//                     decode). Gathers read hidden (L2-resident).
// PDL: table prologue overlaps rowcoef; grid-dep sync before g_coef reads.
// ---------------------------------------------------------------------------
__global__ void __launch_bounds__(H4, 8) fused_kernel(
    const float* __restrict__ hidden,       // [B,S,H]
    const int* __restrict__ ent_tokens,     // [E,T]
    const float* __restrict__ type_table,   // [NT,H]
    const float* __restrict__ conf_w,       // [H]
    const float* __restrict__ conf_b,       // [H]
    float* __restrict__ out_enh,            // [B,S,H]
    float* __restrict__ out_emb) {          // [B,E,H]
    __shared__ float4 s_tab[NT + 1][H4];    // [0..4]=type_table+conf_b, [5]=conf_w
    int tid = threadIdx.x;                  // 0..191
    int h = tid * 4;

    {
        float4 cb4 = *reinterpret_cast<const float4*>(conf_b + h);
        s_tab[NT][tid] = *reinterpret_cast<const float4*>(conf_w + h);
#pragma unroll
        for (int ty = 0; ty < NT; ty++) {
            float4 v = *reinterpret_cast<const float4*>(type_table + ty * HH + h);
            s_tab[ty][tid] = make_float4(v.x + cb4.x, v.y + cb4.y, v.z + cb4.z, v.w + cb4.w);
        }
    }
    __syncthreads();

    cudaGridDependencySynchronize();        // g_coef ready

    if (blockIdx.x < ENH_BLOCKS) {
        // ================= enhance rows: pure linear walk =================
        int row = blockIdx.x;
        const float4* hp = reinterpret_cast<const float4*>(hidden) +
                           (size_t)row * (HH / 4) + tid;
        float4* op = reinterpret_cast<float4*>(out_enh) +
                     (size_t)row * (HH / 4) + tid;
        const uint2* cp = g_coef + row;
        const ptrdiff_t dstep = (ptrdiff_t)ENH_BLOCKS * (HH / 4);

        for (; row < NROW; row += ENH_BLOCKS) {
            uint2 cc = __ldg(cp);
            float4 v = *hp;
            unsigned cnt = cc.x;
            if (cnt) {                       // uniform: row has entities
#pragma unroll
                for (int q = 0; q < NT; q++) {
                    unsigned a = (cnt >> (6 * q)) & 63u;
                    if (a) {                 // uniform
                        float fa = (float)a;
                        float4 t = s_tab[q][tid];
                        v.x += fa * t.x; v.y += fa * t.y;
                        v.z += fa * t.z; v.w += fa * t.w;
                    }
                }
                float cs = __uint_as_float(cc.y);
                float4 t = s_tab[NT][tid];
                v.x += cs * t.x; v.y += cs * t.y; v.z += cs * t.z; v.w += cs * t.w;
            }
            __stcs(op, v);
            hp += dstep; op += dstep; cp += ENH_BLOCKS;
        }
    } else {
        // ================= emb tasks: shift/mask decode =================
        for (int task = (int)blockIdx.x - ENH_BLOCKS; task < NEMB;
             task += EMB_BLOCKS) {
            int b = task >> 7;               // /EE
            int e = task & (EE - 1);
            const float* hb = hidden + (size_t)b * SS * HH;
            float4 acc = make_float4(0.f, 0.f, 0.f, 0.f);
            float a0 = 0.f, a1 = 0.f, a2 = 0.f, a3 = 0.f, a4 = 0.f, ac = 0.f;
#pragma unroll
            for (int t = 0; t < TT_; t++) {
                int s = __ldg(&ent_tokens[e * TT_ + t]);
                uint2 cc = __ldg(&g_coef[b * SS + s]);
                unsigned cnt = cc.x;
                a0 += (float)(cnt & 63u);
                a1 += (float)((cnt >> 6) & 63u);
                a2 += (float)((cnt >> 12) & 63u);
                a3 += (float)((cnt >> 18) & 63u);
                a4 += (float)((cnt >> 24) & 63u);
                ac += __uint_as_float(cc.y);
                float4 v = *reinterpret_cast<const float4*>(hb + (size_t)s * HH + h);
                acc.x += v.x; acc.y += v.y; acc.z += v.z; acc.w += v.w;
            }
            float4 t;
            t = s_tab[0][tid]; acc.x += a0 * t.x; acc.y += a0 * t.y; acc.z += a0 * t.z; acc.w += a0 * t.w;
            t = s_tab[1][tid]; acc.x += a1 * t.x; acc.y += a1 * t.y; acc.z += a1 * t.z; acc.w += a1 * t.w;
            t = s_tab[2][tid]; acc.x += a2 * t.x; acc.y += a2 * t.y; acc.z += a2 * t.z; acc.w += a2 * t.w;
            t = s_tab[3][tid]; acc.x += a3 * t.x; acc.y += a3 * t.y; acc.z += a3 * t.z; acc.w += a3 * t.w;
            t = s_tab[4][tid]; acc.x += a4 * t.x; acc.y += a4 * t.y; acc.z += a4 * t.z; acc.w += a4 * t.w;
            t = s_tab[5][tid]; acc.x += ac * t.x; acc.y += ac * t.y; acc.z += ac * t.z; acc.w += ac * t.w;
            acc.x *= 0.25f; acc.y *= 0.25f; acc.z *= 0.25f; acc.w *= 0.25f;
            __stcs(reinterpret_cast<float4*>(
                out_emb + ((size_t)b * EE + e) * HH + h), acc);
        }
    }
}

// ---------------------------------------------------------------------------
// Inputs in metadata order:
// 0 hidden_states (B,S,H) f32 | 1 entity_types (B,E) i32 | 2 entity_confidences (B,E) f32
// 3 ent_tokens (E,T) i32 | 4 type_table (NT,H) f32 | 5 conf_w (1,H) f32 | 6 conf_b (H) f32
// Output: enhanced (B,S,H) then entity_embeddings (B,E,H), concatenated.
// ---------------------------------------------------------------------------
extern "C" void kernel_launch(void* const* d_in, const int* in_sizes, int n_in,
                              void* d_out, int out_size) {
    const float* hidden   = (const float*)d_in[0];
    const int*   types    = (const int*)d_in[1];
    const float* conf     = (const float*)d_in[2];
    const int*   ent_tok  = (const int*)d_in[3];
    const float* ttab     = (const float*)d_in[4];
    const float* conf_w   = (const float*)d_in[5];
    const float* conf_b   = (const float*)d_in[6];

    float* out_enh = (float*)d_out;
    float* out_emb = out_enh + (size_t)BB * SS * HH;

    rowcoef_kernel<<<BB, 512>>>(ent_tok, types, conf);

    // PDL launch: fused overlaps rowcoef's tail; grid-dependency sync inside
    cudaLaunchConfig_t cfg = {};
    cfg.gridDim = dim3(GRID);
    cfg.blockDim = dim3(H4);
    cfg.dynamicSmemBytes = 0;
    cudaLaunchAttribute attrs[1];
    attrs[0].id = cudaLaunchAttributeProgrammaticStreamSerialization;
    attrs[0].val.programmaticStreamSerializationAllowed = 1;
    cfg.attrs = attrs;
    cfg.numAttrs = 1;
    cudaLaunchKernelEx(&cfg, fused_kernel, hidden, ent_tok, ttab,
                       conf_w, conf_b, out_enh, out_emb);
}